// round 9
// baseline (speedup 1.0000x reference)
#include <cuda_runtime.h>
#include <cstdint>

// ---------------- Problem dims ----------------
static constexpr int T   = 20;
static constexpr int B   = 1024;
static constexpr int IN  = 2048;
static constexpr int OUT = 2048;
static constexpr int M   = T * B;          // 20480
static constexpr int K   = IN;             // 2048
static constexpr int N   = OUT;            // 2048

static constexpr int KT  = K / 32;         // 64 k-tiles of 32
static constexpr int MT  = M / 16;         // 1280 m-tiles of 16
static constexpr int NT  = N / 8;          // 256 n-tiles of 8

// 3-digit int8 decomposition of w: w = S1*d1 + S2*d2 + S3*d3, |d| <= 127
static constexpr float S1 = 1.0f / 127.0f;
static constexpr float S2 = S1 / 254.0f;
static constexpr float S3 = S2 / 254.0f;

// GEMM tiling: CTA 128x128x64(=2 k-tiles), 256 threads, 8 warps (2m x 4n), warp 64x32
static constexpr int BM = 128;
static constexpr int BN = 128;
static constexpr int STAGES = 4;
static constexpr int NCHUNK = K / 64;      // 32 chunks of 2 k-tiles

static constexpr int A_STAGE_B = 8 * 2 * 512;   // 8 mt x 2 kt x 512B = 8192
static constexpr int W_STAGE_B = 16 * 2 * 256;  // 16 nt x 2 kt x 256B = 8192
static constexpr int STAGE_B   = A_STAGE_B + W_STAGE_B;  // 16384
static constexpr int SMEM_B    = STAGES * STAGE_B;       // 65536

// ---------------- scratch (frag-major layouts) ----------------
__device__ uint4 g_x8[(size_t)MT * KT * 32];          // 42 MB  A fragments
__device__ uint2 g_wd[3][(size_t)NT * KT * 32];       // 3 x 4 MB  W digit fragments
__device__ float g_cur[(size_t)M * N];                // 168 MB

// ---------------- helpers ----------------
__device__ __forceinline__ uint32_t smem_u32(const void* p) {
    uint32_t a;
    asm("{ .reg .u64 t; cvta.to.shared.u64 t, %1; cvt.u32.u64 %0, t; }" : "=r"(a) : "l"(p));
    return a;
}
__device__ __forceinline__ void cp16(uint32_t dst, const void* src) {
    asm volatile("cp.async.cg.shared.global [%0], [%1], 16;\n" :: "r"(dst), "l"(src));
}
__device__ __forceinline__ void cp8(uint32_t dst, const void* src) {
    asm volatile("cp.async.ca.shared.global [%0], [%1], 8;\n" :: "r"(dst), "l"(src));
}
__device__ __forceinline__ void lds128(uint32_t* r, uint32_t addr) {
    asm volatile("ld.shared.v4.u32 {%0,%1,%2,%3}, [%4];"
                 : "=r"(r[0]), "=r"(r[1]), "=r"(r[2]), "=r"(r[3]) : "r"(addr));
}
__device__ __forceinline__ void lds64(uint32_t* r, uint32_t addr) {
    asm volatile("ld.shared.v2.u32 {%0,%1}, [%2];"
                 : "=r"(r[0]), "=r"(r[1]) : "r"(addr));
}
__device__ __forceinline__ void imma16832(int* d, const uint32_t* a, uint32_t b0, uint32_t b1) {
    asm volatile(
        "mma.sync.aligned.m16n8k32.row.col.s32.s8.s8.s32 "
        "{%0,%1,%2,%3}, {%4,%5,%6,%7}, {%8,%9}, {%0,%1,%2,%3};"
        : "+r"(d[0]), "+r"(d[1]), "+r"(d[2]), "+r"(d[3])
        : "r"(a[0]), "r"(a[1]), "r"(a[2]), "r"(a[3]), "r"(b0), "r"(b1));
}
__device__ __forceinline__ int clamp127(int v) {
    return v < -127 ? -127 : (v > 127 ? 127 : v);
}

// ---------------- prep: W -> 3 int8 digits, fragment-major ----------------
__global__ void split_w_kernel(const float* __restrict__ w) {
    int idx = blockIdx.x * blockDim.x + threadIdx.x;
    if (idx >= NT * KT * 32) return;
    int lane = idx & 31;
    int kt   = (idx >> 5) & (KT - 1);
    int nt   = idx >> 11;
    int n = nt * 8 + (lane >> 2);
    int k = kt * 32 + (lane & 3) * 4;

    uint32_t b[3][2];
    #pragma unroll
    for (int reg = 0; reg < 2; reg++) {
        float4 v = *reinterpret_cast<const float4*>(&w[(size_t)n * K + k + reg * 16]);
        float vs[4] = {v.x, v.y, v.z, v.w};
        uint32_t p1 = 0, p2 = 0, p3 = 0;
        #pragma unroll
        for (int c = 0; c < 4; c++) {
            float val = vs[c];
            int d1 = clamp127(__float2int_rn(val * (1.0f / S1)));
            float r1 = fmaf((float)-d1, S1, val);
            int d2 = clamp127(__float2int_rn(r1 * (1.0f / S2)));
            float r2 = fmaf((float)-d2, S2, r1);
            int d3 = clamp127(__float2int_rn(r2 * (1.0f / S3)));
            p1 |= (uint32_t)(d1 & 0xFF) << (8 * c);
            p2 |= (uint32_t)(d2 & 0xFF) << (8 * c);
            p3 |= (uint32_t)(d3 & 0xFF) << (8 * c);
        }
        b[0][reg] = p1; b[1][reg] = p2; b[2][reg] = p3;
    }
    #pragma unroll
    for (int d = 0; d < 3; d++)
        g_wd[d][idx] = make_uint2(b[d][0], b[d][1]);
}

// ---------------- prep: x (fp32 0/1) -> int8 fragment-major ----------------
__global__ void conv_x_kernel(const float* __restrict__ x) {
    int idx = blockIdx.x * blockDim.x + threadIdx.x;
    if (idx >= MT * KT * 32) return;
    int lane = idx & 31;
    int kt   = (idx >> 5) & (KT - 1);
    int mt   = idx >> 11;
    int m = mt * 16 + (lane >> 2);
    int k = kt * 32 + (lane & 3) * 4;

    uint32_t regs[4];
    #pragma unroll
    for (int r = 0; r < 4; r++) {
        int mm = m + ((r & 1) ? 8 : 0);
        int kk = k + ((r & 2) ? 16 : 0);
        float4 v = *reinterpret_cast<const float4*>(&x[(size_t)mm * K + kk]);
        uint32_t p = 0;
        p |= (v.x != 0.0f) ? 0x01u : 0;
        p |= (v.y != 0.0f) ? 0x0100u : 0;
        p |= (v.z != 0.0f) ? 0x010000u : 0;
        p |= (v.w != 0.0f) ? 0x01000000u : 0;
        regs[r] = p;
    }
    g_x8[idx] = make_uint4(regs[0], regs[1], regs[2], regs[3]);
}

// ---------------- GEMM: 3 sequential int8 digit sweeps, s32 accum ----------------
__global__ void __launch_bounds__(256, 1) gemm_kernel() {
    extern __shared__ char smem[];
    const uint32_t sb = smem_u32(smem);
    const int tid = threadIdx.x;
    const int lid = tid & 31;
    const int wid = tid >> 5;

    const int m0 = blockIdx.y * BM;
    const int n0 = blockIdx.x * BN;
    const int mt0 = m0 >> 4;
    const int nt0 = n0 >> 3;

    const int wm_t = (wid & 1) * 4;
    const int wn_t = (wid >> 1) * 4;

    float accf[4][4][4];
    #pragma unroll
    for (int i = 0; i < 4; i++)
        #pragma unroll
        for (int j = 0; j < 4; j++)
            #pragma unroll
            for (int r = 0; r < 4; r++) accf[i][j][r] = 0.0f;

    const float SD[3] = {S1, S2, S3};

    // digits smallest-first (d=2,1,0): fp32 combine error = ~1 final rounding
    #pragma unroll 1
    for (int d = 2; d >= 0; d--) {
        const uint2* wsrc = g_wd[d];

        auto issue = [&](int c) {
            if (c < NCHUNK) {
                const uint32_t base = sb + (c % STAGES) * STAGE_B;
                #pragma unroll
                for (int i = 0; i < 2; i++) {
                    int id = tid + i * 256;
                    int mt_l = id >> 6, kt_l = (id >> 5) & 1, ln = id & 31;
                    int kt_g = c * 2 + kt_l;
                    cp16(base + (uint32_t)id * 16,
                         &g_x8[((size_t)(mt0 + mt_l) * KT + kt_g) * 32 + ln]);
                }
                #pragma unroll
                for (int i = 0; i < 4; i++) {
                    int id = tid + i * 256;
                    int nt_l = id >> 6, kt_l = (id >> 5) & 1, ln = id & 31;
                    int kt_g = c * 2 + kt_l;
                    cp8(base + A_STAGE_B + (uint32_t)id * 8,
                        &wsrc[((size_t)(nt0 + nt_l) * KT + kt_g) * 32 + ln]);
                }
            }
            asm volatile("cp.async.commit_group;\n" ::: "memory");
        };

        int acc[4][4][4];
        #pragma unroll
        for (int i = 0; i < 4; i++)
            #pragma unroll
            for (int j = 0; j < 4; j++)
                #pragma unroll
                for (int r = 0; r < 4; r++) acc[i][j][r] = 0;

        issue(0); issue(1); issue(2);

        #pragma unroll 1
        for (int c = 0; c < NCHUNK; c++) {
            // 3 groups in flight; wait until <=2 pending => group c complete.
            asm volatile("cp.async.wait_group 2;\n" ::: "memory");
            __syncthreads();
            issue(c + 3);

            const uint32_t sA = sb + (c % STAGES) * STAGE_B;
            const uint32_t sW = sA + A_STAGE_B;

            #pragma unroll
            for (int kt = 0; kt < 2; kt++) {
                uint32_t a[4][4];
                #pragma unroll
                for (int mi = 0; mi < 4; mi++)
                    lds128(a[mi], sA + (uint32_t)((((wm_t + mi) * 2 + kt) * 32 + lid) * 16));
                uint32_t b[4][2];
                #pragma unroll
                for (int nj = 0; nj < 4; nj++)
                    lds64(b[nj], sW + (uint32_t)((((wn_t + nj) * 2 + kt) * 32 + lid) * 8));
                #pragma unroll
                for (int mi = 0; mi < 4; mi++)
                    #pragma unroll
                    for (int nj = 0; nj < 4; nj++)
                        imma16832(acc[mi][nj], a[mi], b[nj][0], b[nj][1]);
            }
        }
        asm volatile("cp.async.wait_group 0;\n" ::: "memory");
        __syncthreads();

        const float sd = SD[d];
        #pragma unroll
        for (int i = 0; i < 4; i++)
            #pragma unroll
            for (int j = 0; j < 4; j++)
                #pragma unroll
                for (int r = 0; r < 4; r++)
                    accf[i][j][r] = fmaf(sd, (float)acc[i][j][r], accf[i][j][r]);
    }

    // epilogue
    const int r_base = m0 + (wid & 1) * 64 + (lid >> 2);
    const int c_base = n0 + (wid >> 1) * 32 + (lid & 3) * 2;
    #pragma unroll
    for (int mi = 0; mi < 4; mi++) {
        #pragma unroll
        for (int nj = 0; nj < 4; nj++) {
            float2 v01 = make_float2(accf[mi][nj][0], accf[mi][nj][1]);
            float2 v23 = make_float2(accf[mi][nj][2], accf[mi][nj][3]);
            *reinterpret_cast<float2*>(
                &g_cur[(size_t)(r_base + mi * 16) * N + c_base + nj * 8]) = v01;
            *reinterpret_cast<float2*>(
                &g_cur[(size_t)(r_base + mi * 16 + 8) * N + c_base + nj * 8]) = v23;
        }
    }
}

// ---------------- LIF scan kernel ----------------
__global__ void scan_kernel(float* __restrict__ out) {
    const int id = blockIdx.x * blockDim.x + threadIdx.x;
    const int o = id & (N - 1);
    const int b = id >> 11;
    const float alpha_s = 0.8f;
    const float alpha_m = 0.95f;
    const float inv_tau = 0.05f;
    float V = 0.0f, I = 0.0f;
    #pragma unroll
    for (int t = 0; t < T; t++) {
        const size_t idx = ((size_t)(t * B + b)) * N + o;
        float cu = g_cur[idx];
        I = alpha_s * I + cu;
        V = alpha_m * V + inv_tau * I;
        float s = (V >= 1.0f) ? 1.0f : 0.0f;
        out[idx] = s;
        V = (V >= 1.0f) ? 0.0f : V;
    }
}

// ---------------- launch ----------------
extern "C" void kernel_launch(void* const* d_in, const int* in_sizes, int n_in,
                              void* d_out, int out_size) {
    const float* x = (const float*)d_in[0];       // [T, B, IN] fp32, binary
    const float* w = (const float*)d_in[1];       // [OUT, IN]  fp32
    float* out = (float*)d_out;                   // [T, B, OUT] fp32

    cudaFuncSetAttribute(gemm_kernel, cudaFuncAttributeMaxDynamicSharedMemorySize, SMEM_B);

    split_w_kernel<<<(NT * KT * 32) / 256, 256>>>(w);
    conv_x_kernel<<<(MT * KT * 32) / 256, 256>>>(x);
    gemm_kernel<<<dim3(N / BN, M / BM), 256, SMEM_B>>>();
    scan_kernel<<<(B * N) / 256, 256>>>(out);
}

// round 10
// speedup vs baseline: 4.4462x; 4.4462x over previous
#include <cuda_runtime.h>
#include <cuda_fp16.h>
#include <cstdint>

// ---------------- Problem dims ----------------
static constexpr int T   = 20;
static constexpr int B   = 1024;
static constexpr int IN  = 2048;
static constexpr int OUT = 2048;
static constexpr int M   = T * B;          // 20480
static constexpr int K   = IN;             // 2048
static constexpr int N   = OUT;            // 2048

// GEMM tiling: 128x128x64, 256 threads, 2 CTAs/SM, 2 stages, SW128 swizzle (no pad)
static constexpr int BM = 128;
static constexpr int BN = 128;
static constexpr int BK = 64;              // 64 halfs = 128B row
static constexpr int NCHUNK = K / BK;      // 32

static constexpr int TILE_B  = 128 * 128;          // 16384 B per matrix tile
static constexpr int STAGE_B = 3 * TILE_B;         // A + Bhi + Blo = 49152
static constexpr int SMEM_B  = 2 * STAGE_B;        // 98304 (2 CTAs/SM -> 192KB)

// ---------------- scratch (no cudaMalloc allowed) ----------------
__device__ __half g_xh [(size_t)M * K];    // 84 MB  x in fp16 (exact: x is 0/1)
__device__ __half g_whi[(size_t)N * K];    // 8 MB   weight hi (fp16)
__device__ __half g_wlo[(size_t)N * K];    // 8 MB   weight lo (fp16 residual)
__device__ float  g_cur[(size_t)M * N];    // 168 MB GEMM result (fp32)

// ---------------- helpers ----------------
__device__ __forceinline__ uint32_t smem_u32(const void* p) {
    uint32_t a;
    asm("{ .reg .u64 t; cvta.to.shared.u64 t, %1; cvt.u32.u64 %0, t; }" : "=r"(a) : "l"(p));
    return a;
}
__device__ __forceinline__ void cp16(uint32_t dst, const void* src) {
    asm volatile("cp.async.cg.shared.global [%0], [%1], 16;\n" :: "r"(dst), "l"(src));
}
__device__ __forceinline__ void ldm_x4(uint32_t* r, uint32_t addr) {
    asm volatile("ldmatrix.sync.aligned.m8n8.x4.shared.b16 {%0,%1,%2,%3}, [%4];"
                 : "=r"(r[0]), "=r"(r[1]), "=r"(r[2]), "=r"(r[3]) : "r"(addr));
}
__device__ __forceinline__ void mma16816(float* d, const uint32_t* a, uint32_t b0, uint32_t b1) {
    asm volatile(
        "mma.sync.aligned.m16n8k16.row.col.f32.f16.f16.f32 "
        "{%0,%1,%2,%3}, {%4,%5,%6,%7}, {%8,%9}, {%0,%1,%2,%3};"
        : "+f"(d[0]), "+f"(d[1]), "+f"(d[2]), "+f"(d[3])
        : "r"(a[0]), "r"(a[1]), "r"(a[2]), "r"(a[3]), "r"(b0), "r"(b1));
}
__device__ __forceinline__ uint32_t sw128(uint32_t off) {
    return off ^ ((off >> 3) & 0x70);       // XOR 16B-chunk with row(within 8)
}

// ---------------- prep kernels ----------------
__global__ void split_w_kernel(const float* __restrict__ w) {
    int i = blockIdx.x * blockDim.x + threadIdx.x;
    if (i < N * K) {
        float v = w[i];
        __half hi = __float2half_rn(v);
        float r = v - __half2float(hi);
        g_whi[i] = hi;
        g_wlo[i] = __float2half_rn(r);
    }
}

__global__ void conv_x_kernel(const float* __restrict__ x) {
    size_t i = (size_t)blockIdx.x * blockDim.x + threadIdx.x;
    if (i < ((size_t)M * K) / 4) {
        float4 v = reinterpret_cast<const float4*>(x)[i];
        __half2 h0 = __floats2half2_rn(v.x, v.y);
        __half2 h1 = __floats2half2_rn(v.z, v.w);
        uint2 packed;
        packed.x = *reinterpret_cast<uint32_t*>(&h0);
        packed.y = *reinterpret_cast<uint32_t*>(&h1);
        reinterpret_cast<uint2*>(g_xh)[i] = packed;
    }
}

// ---------------- GEMM: 128x128x64, 256 thr, 2 CTAs/SM, fp16 2-split mma.sync ----------------
__global__ void __launch_bounds__(256, 2) gemm_kernel() {
    extern __shared__ char smem[];
    const uint32_t sb = smem_u32(smem);
    const int tid = threadIdx.x;
    const int lid = tid & 31;
    const int wid = tid >> 5;

    const int m0 = blockIdx.y * BM;
    const int n0 = blockIdx.x * BN;

    // warp layout: 2 (m) x 4 (n), warp tile 64x32
    const int wm = (wid & 1) * 64;
    const int wn = (wid >> 1) * 32;

    // ldmatrix lane addressing (pre-swizzle row/chunk parts)
    const int a_row = wm + (lid & 15);
    const int a_kb  = (lid >> 4) << 4;               // 0 or 16 bytes (k half-offset)
    const int b_row = wn + (lid & 7) + ((lid >> 4) << 3);
    const int b_kb  = ((lid >> 3) & 1) << 4;         // 0 or 16 bytes

    auto issue = [&](int c) {
        if (c < NCHUNK) {
            const int k0 = c * BK;
            const uint32_t base = sb + (c & 1) * STAGE_B;
            // each tile: 128 rows x 8 chunks of 16B = 1024 cp16; 4 per thread per tile
            #pragma unroll
            for (int i = 0; i < 4; i++) {
                int id = tid + i * 256;
                int row = id >> 3, kc = id & 7;
                uint32_t soff = sw128((uint32_t)(row * 128 + kc * 16));
                const size_t gco = k0 + kc * 8;
                cp16(base + soff,              g_xh  + (size_t)(m0 + row) * K + gco);
                cp16(base + TILE_B + soff,     g_whi + (size_t)(n0 + row) * K + gco);
                cp16(base + 2 * TILE_B + soff, g_wlo + (size_t)(n0 + row) * K + gco);
            }
        }
        asm volatile("cp.async.commit_group;\n" ::: "memory");
    };

    issue(0);

    float acc[4][4][4];
    #pragma unroll
    for (int i = 0; i < 4; i++)
        #pragma unroll
        for (int j = 0; j < 4; j++)
            #pragma unroll
            for (int r = 0; r < 4; r++) acc[i][j][r] = 0.0f;

    #pragma unroll 1
    for (int c = 0; c < NCHUNK; c++) {
        asm volatile("cp.async.wait_group 0;\n" ::: "memory");
        __syncthreads();
        issue(c + 1);

        const uint32_t sA  = sb + (c & 1) * STAGE_B;
        const uint32_t sBh = sA + TILE_B;
        const uint32_t sBl = sA + 2 * TILE_B;

        #pragma unroll
        for (int ks = 0; ks < 4; ks++) {
            uint32_t a[4][4];
            #pragma unroll
            for (int mi = 0; mi < 4; mi++) {
                uint32_t off = sw128((uint32_t)((a_row + mi * 16) * 128 + ks * 32 + a_kb));
                ldm_x4(a[mi], sA + off);
            }
            // stream B: one bi (16 n-cols, hi+lo) live at a time -> 8 live b regs
            #pragma unroll
            for (int bi = 0; bi < 2; bi++) {
                uint32_t off = sw128((uint32_t)((b_row + bi * 16) * 128 + ks * 32 + b_kb));
                uint32_t bh[4], bl[4];
                ldm_x4(bh, sBh + off);
                ldm_x4(bl, sBl + off);
                #pragma unroll
                for (int mi = 0; mi < 4; mi++) {
                    #pragma unroll
                    for (int njj = 0; njj < 2; njj++) {
                        const int nj = bi * 2 + njj, pr = njj * 2;
                        mma16816(acc[mi][nj], a[mi], bh[pr], bh[pr + 1]);
                        mma16816(acc[mi][nj], a[mi], bl[pr], bl[pr + 1]);
                    }
                }
            }
        }
        __syncthreads();
    }

    // epilogue: write fp32 accumulators to g_cur
    const int r_base = m0 + wm + (lid >> 2);
    const int c_base = n0 + wn + (lid & 3) * 2;
    #pragma unroll
    for (int mi = 0; mi < 4; mi++) {
        #pragma unroll
        for (int nj = 0; nj < 4; nj++) {
            float2 v01 = make_float2(acc[mi][nj][0], acc[mi][nj][1]);
            float2 v23 = make_float2(acc[mi][nj][2], acc[mi][nj][3]);
            *reinterpret_cast<float2*>(
                &g_cur[(size_t)(r_base + mi * 16) * N + c_base + nj * 8]) = v01;
            *reinterpret_cast<float2*>(
                &g_cur[(size_t)(r_base + mi * 16 + 8) * N + c_base + nj * 8]) = v23;
        }
    }
}

// ---------------- LIF scan kernel ----------------
__global__ void scan_kernel(float* __restrict__ out) {
    const int id = blockIdx.x * blockDim.x + threadIdx.x;
    const int o = id & (N - 1);
    const int b = id >> 11;
    const float alpha_s = 0.8f;
    const float alpha_m = 0.95f;
    const float inv_tau = 0.05f;
    float V = 0.0f, I = 0.0f;
    #pragma unroll
    for (int t = 0; t < T; t++) {
        const size_t idx = ((size_t)(t * B + b)) * N + o;
        float cu = g_cur[idx];
        I = alpha_s * I + cu;
        V = alpha_m * V + inv_tau * I;
        float s = (V >= 1.0f) ? 1.0f : 0.0f;
        out[idx] = s;
        V = (V >= 1.0f) ? 0.0f : V;
    }
}

// ---------------- launch ----------------
extern "C" void kernel_launch(void* const* d_in, const int* in_sizes, int n_in,
                              void* d_out, int out_size) {
    const float* x = (const float*)d_in[0];       // [T, B, IN] fp32, binary
    const float* w = (const float*)d_in[1];       // [OUT, IN]  fp32
    float* out = (float*)d_out;                   // [T, B, OUT] fp32

    cudaFuncSetAttribute(gemm_kernel, cudaFuncAttributeMaxDynamicSharedMemorySize, SMEM_B);

    split_w_kernel<<<(N * K + 255) / 256, 256>>>(w);
    conv_x_kernel<<<(int)(((size_t)M * K / 4 + 255) / 256), 256>>>(x);
    gemm_kernel<<<dim3(N / BN, M / BM), 256, SMEM_B>>>();
    scan_kernel<<<(B * N) / 256, 256>>>(out);
}